// round 1
// baseline (speedup 1.0000x reference)
#include <cuda_runtime.h>
#include <math.h>

#define NN 8192
#define DD 256
#define KK 16
#define KSEL 17          // K+1 (self included during selection)
#define BM 64
#define BN 64
#define RS (DD + 4)      // smem row stride in floats (260): strided col map -> conflict-free-ish

__device__ float g_sq[NN];
__device__ unsigned long long g_best[NN * KSEL];

// monotone float->uint mapping (order-preserving incl. negatives)
__device__ __forceinline__ unsigned int mono(float f) {
    unsigned int u = __float_as_uint(f);
    return (u & 0x80000000u) ? ~u : (u | 0x80000000u);
}

// ---------------- Kernel A: row squared norms ----------------
__global__ void sq_kernel(const float* __restrict__ feats) {
    int gw = (blockIdx.x * blockDim.x + threadIdx.x) >> 5;
    int lane = threadIdx.x & 31;
    if (gw >= NN) return;
    const float4* rowp = (const float4*)(feats + (size_t)gw * DD);
    float4 a = rowp[lane];
    float4 b = rowp[lane + 32];
    float s = a.x*a.x + a.y*a.y + a.z*a.z + a.w*a.w
            + b.x*b.x + b.y*b.y + b.z*b.z + b.w*b.w;
    #pragma unroll
    for (int o = 16; o; o >>= 1) s += __shfl_xor_sync(0xffffffffu, s, o);
    if (lane == 0) g_sq[gw] = s;
}

// ---------------- Kernel B: all-pairs distances + streaming top-17 ----------------
struct SmemB {
    float As[BM][RS];
    float Bs[BN][RS];
    float sqB[BN];
    float thr[BM];
    int   cnt[BM];
    unsigned long long best[BM][KSEL];
    unsigned long long cand[BM][BN];
};

__global__ void __launch_bounds__(256, 1) knn_kernel(const float* __restrict__ feats) {
    extern __shared__ char smem_raw[];
    SmemB& sm = *reinterpret_cast<SmemB*>(smem_raw);
    const int tid = threadIdx.x;
    const int i0 = blockIdx.x * BM;
    const int tx = tid & 15;
    const int ty = tid >> 4;

    // load A tile: 64 rows x 256 floats = 4096 float4
    {
        const float4* src = (const float4*)(feats + (size_t)i0 * DD);
        #pragma unroll
        for (int t = 0; t < (BM * DD / 4) / 256; ++t) {
            int idx = t * 256 + tid;
            int r = idx >> 6, c = idx & 63;
            *(float4*)&sm.As[r][c * 4] = src[idx];
        }
    }
    if (tid < BM) {
        sm.thr[tid] = __int_as_float(0x7f800000);   // +inf
        sm.cnt[tid] = 0;
        #pragma unroll
        for (int t = 0; t < KSEL; ++t) sm.best[tid][t] = 0xFFFFFFFFFFFFFFFFull;
    }
    __syncthreads();

    for (int jt = 0; jt < NN / BN; ++jt) {
        const int j0 = jt * BN;
        // load B tile
        {
            const float4* src = (const float4*)(feats + (size_t)j0 * DD);
            #pragma unroll
            for (int t = 0; t < (BN * DD / 4) / 256; ++t) {
                int idx = t * 256 + tid;
                int r = idx >> 6, c = idx & 63;
                *(float4*)&sm.Bs[r][c * 4] = src[idx];
            }
        }
        if (tid < BN) sm.sqB[tid] = g_sq[j0 + tid];
        __syncthreads();

        // 4x4 register tile, strided row/col ownership: r = ty+16a, c = tx+16b
        float acc[4][4];
        #pragma unroll
        for (int a = 0; a < 4; ++a)
            #pragma unroll
            for (int b = 0; b < 4; ++b) acc[a][b] = 0.f;

        #pragma unroll 4
        for (int k = 0; k < DD; k += 4) {
            float4 av[4], bv[4];
            #pragma unroll
            for (int a = 0; a < 4; ++a) av[a] = *(const float4*)&sm.As[ty + 16 * a][k];
            #pragma unroll
            for (int b = 0; b < 4; ++b) bv[b] = *(const float4*)&sm.Bs[tx + 16 * b][k];
            #pragma unroll
            for (int a = 0; a < 4; ++a)
                #pragma unroll
                for (int b = 0; b < 4; ++b) {
                    acc[a][b] = fmaf(av[a].x, bv[b].x, acc[a][b]);
                    acc[a][b] = fmaf(av[a].y, bv[b].y, acc[a][b]);
                    acc[a][b] = fmaf(av[a].z, bv[b].z, acc[a][b]);
                    acc[a][b] = fmaf(av[a].w, bv[b].w, acc[a][b]);
                }
        }

        // candidate pass: rank key = sq_j - 2*s  (sq_i is per-row constant)
        #pragma unroll
        for (int a = 0; a < 4; ++a) {
            const int r = ty + 16 * a;
            const float thr = sm.thr[r];
            #pragma unroll
            for (int b = 0; b < 4; ++b) {
                const int c = tx + 16 * b;
                float val = fmaf(-2.f, acc[a][b], sm.sqB[c]);
                if (val < thr) {
                    int p = atomicAdd(&sm.cnt[r], 1);   // <= 64 per row per tile, can't overflow
                    sm.cand[r][p] = ((unsigned long long)mono(val) << 32)
                                  | (unsigned int)(j0 + c);
                }
            }
        }
        __syncthreads();

        // flush: one thread per row merges candidates into sorted top-17
        if (tid < BM) {
            int n = sm.cnt[tid];
            sm.cnt[tid] = 0;
            for (int q = 0; q < n; ++q) {
                unsigned long long key = sm.cand[tid][q];
                if (key < sm.best[tid][KSEL - 1]) {
                    int p = KSEL - 1;
                    while (p > 0 && sm.best[tid][p - 1] > key) {
                        sm.best[tid][p] = sm.best[tid][p - 1];
                        --p;
                    }
                    sm.best[tid][p] = key;
                }
            }
            unsigned int mt = (unsigned int)(sm.best[tid][KSEL - 1] >> 32);
            unsigned int u = (mt & 0x80000000u) ? (mt ^ 0x80000000u) : ~mt;  // inverse mono
            sm.thr[tid] = __uint_as_float(u);
        }
        __syncthreads();
    }

    for (int idx = tid; idx < BM * KSEL; idx += 256) {
        int r = idx / KSEL, t = idx % KSEL;
        g_best[(size_t)(i0 + r) * KSEL + t] = sm.best[r][t];
    }
}

// ---------------- Kernel C: mutual mask + sparse softmax + AV + residual + normalize ----------------
__global__ void fuse_kernel(const float* __restrict__ feats, float* __restrict__ out) {
    int gw = (blockIdx.x * blockDim.x + threadIdx.x) >> 5;
    int lane = threadIdx.x & 31;
    if (gw >= NN) return;
    const int row = gw;
    const float* base = feats + (size_t)row * DD;
    float4 a0 = *(const float4*)(base + lane * 4);
    float4 a1 = *(const float4*)(base + 128 + lane * 4);
    float own[8] = {a0.x, a0.y, a0.z, a0.w, a1.x, a1.y, a1.z, a1.w};

    // extract the 16 neighbors (drop self); lane l keeps neighbor l
    int my_nbr = -1;
    int cnt = 0;
    #pragma unroll
    for (int t = 0; t < KSEL; ++t) {
        unsigned long long key = g_best[(size_t)row * KSEL + t];
        int j = (int)(unsigned int)(key & 0xffffffffull);
        if (j != row && cnt < KK) {
            if (cnt == lane) my_nbr = j;
            cnt++;
        }
    }

    // mutual test: is `row` in neighbor's top-17 list?
    bool found = false;
    if (lane < KK && my_nbr >= 0) {
        #pragma unroll
        for (int t = 0; t < KSEL; ++t) {
            unsigned long long key = g_best[(size_t)my_nbr * KSEL + t];
            if ((int)(unsigned int)(key & 0xffffffffull) == row) found = true;
        }
    }
    unsigned int mmask = __ballot_sync(0xffffffffu, found) & 0xffffu;

    // online softmax over {diag logit = 1.0 (vector = own)} U {exact fp32 scores of mutual nbrs}
    float m = 1.0f, Z = 1.0f;
    float acc[8];
    #pragma unroll
    for (int e = 0; e < 8; ++e) acc[e] = own[e];

    for (int l = 0; l < KK; ++l) {
        if (!((mmask >> l) & 1u)) continue;
        int j = __shfl_sync(0xffffffffu, my_nbr, l);
        const float* nb = feats + (size_t)j * DD;
        float4 b0 = *(const float4*)(nb + lane * 4);
        float4 b1 = *(const float4*)(nb + 128 + lane * 4);
        float v[8] = {b0.x, b0.y, b0.z, b0.w, b1.x, b1.y, b1.z, b1.w};
        float p = 0.f;
        #pragma unroll
        for (int e = 0; e < 8; ++e) p = fmaf(own[e], v[e], p);
        #pragma unroll
        for (int o = 16; o; o >>= 1) p += __shfl_xor_sync(0xffffffffu, p, o);
        if (p > m) {
            float f = expf(m - p);
            Z = Z * f + 1.0f;
            #pragma unroll
            for (int e = 0; e < 8; ++e) acc[e] = fmaf(acc[e], f, v[e]);
            m = p;
        } else {
            float w = expf(p - m);
            Z += w;
            #pragma unroll
            for (int e = 0; e < 8; ++e) acc[e] = fmaf(w, v[e], acc[e]);
        }
    }

    float invZ = 1.0f / Z;
    float fcm[8];
    float ss = 0.f;
    #pragma unroll
    for (int e = 0; e < 8; ++e) {
        fcm[e] = fmaf(acc[e], invZ, own[e]);   // residual + attn@V
        ss = fmaf(fcm[e], fcm[e], ss);
    }
    #pragma unroll
    for (int o = 16; o; o >>= 1) ss += __shfl_xor_sync(0xffffffffu, ss, o);
    float inv = 1.0f / fmaxf(sqrtf(ss), 1e-12f);

    float* op = out + (size_t)row * DD;
    float4 r0 = make_float4(fcm[0] * inv, fcm[1] * inv, fcm[2] * inv, fcm[3] * inv);
    float4 r1 = make_float4(fcm[4] * inv, fcm[5] * inv, fcm[6] * inv, fcm[7] * inv);
    *(float4*)(op + lane * 4) = r0;
    *(float4*)(op + 128 + lane * 4) = r1;
}

// ---------------- launch ----------------
extern "C" void kernel_launch(void* const* d_in, const int* in_sizes, int n_in,
                              void* d_out, int out_size) {
    const float* feats = (const float*)d_in[0];
    float* out = (float*)d_out;
    (void)in_sizes; (void)n_in; (void)out_size;

    cudaFuncSetAttribute(knn_kernel, cudaFuncAttributeMaxDynamicSharedMemorySize,
                         (int)sizeof(SmemB));

    sq_kernel<<<NN / 8, 256>>>(feats);
    knn_kernel<<<NN / BM, 256, sizeof(SmemB)>>>(feats);
    fuse_kernel<<<NN / 8, 256>>>(feats, out);
}

// round 3
// speedup vs baseline: 1.2184x; 1.2184x over previous
#include <cuda_runtime.h>
#include <math.h>

#define NN 8192
#define DD 256
#define KK 16
#define KSEL 17
#define MSEL 32          // approx survivors per row (screening)
#define BM 64
#define BN 64
#define RS 260           // smem row stride (floats): 260 % 32 == 4 -> conflict-free frag loads
#define SS_PAD 68        // score tile row stride

__device__ float g_sq[NN];
__device__ unsigned long long g_cand[NN * MSEL];   // approx top-32 (screened)
__device__ unsigned long long g_best[NN * KSEL];   // exact top-17

__device__ __forceinline__ unsigned int mono(float f) {
    unsigned int u = __float_as_uint(f);
    return (u & 0x80000000u) ? ~u : (u | 0x80000000u);
}

__device__ __forceinline__ unsigned int f2tf(float f) {
    unsigned int r;
    asm("cvt.rna.tf32.f32 %0, %1;" : "=r"(r) : "f"(f));
    return r;
}

// ---------------- Kernel A: row squared norms ----------------
__global__ void sq_kernel(const float* __restrict__ feats) {
    int gw = (blockIdx.x * blockDim.x + threadIdx.x) >> 5;
    int lane = threadIdx.x & 31;
    if (gw >= NN) return;
    const float4* rowp = (const float4*)(feats + (size_t)gw * DD);
    float4 a = rowp[lane];
    float4 b = rowp[lane + 32];
    float s = a.x*a.x + a.y*a.y + a.z*a.z + a.w*a.w
            + b.x*b.x + b.y*b.y + b.z*b.z + b.w*b.w;
    #pragma unroll
    for (int o = 16; o; o >>= 1) s += __shfl_xor_sync(0xffffffffu, s, o);
    if (lane == 0) g_sq[gw] = s;
}

// ---------------- Kernel B: tf32 tensor scores + streaming approx top-32 ----------------
struct SmemB {
    float As[BM][RS];                       // tf32 bit patterns
    float Bs[BN][RS];                       // tf32 bit patterns
    float Ss[BM][SS_PAD];                   // fp32 score tile
    float sqB[BN];
    float thr[BM];
    int   cnt[BM];
    unsigned long long best[BM][MSEL];
    unsigned long long cand[BM][BN];
};

__global__ void __launch_bounds__(256, 1) knn_kernel(const float* __restrict__ feats) {
    extern __shared__ char smem_raw[];
    SmemB& sm = *reinterpret_cast<SmemB*>(smem_raw);
    const int tid  = threadIdx.x;
    const int lane = tid & 31;
    const int w    = tid >> 5;
    const int wr   = w >> 1;            // 0..3
    const int wc   = w & 1;             // 0..1
    const int g    = lane >> 2;
    const int q    = lane & 3;
    const int i0   = blockIdx.x * BM;
    const int tx   = tid & 15;
    const int ty   = tid >> 4;

    {
        const float4* src = (const float4*)(feats + (size_t)i0 * DD);
        #pragma unroll
        for (int t = 0; t < 16; ++t) {
            int idx = t * 256 + tid;
            int r = idx >> 6, c4 = idx & 63;
            float4 v = src[idx];
            uint4 u = make_uint4(f2tf(v.x), f2tf(v.y), f2tf(v.z), f2tf(v.w));
            *(uint4*)&sm.As[r][c4 * 4] = u;
        }
    }
    if (tid < BM) {
        sm.thr[tid] = __int_as_float(0x7f800000);
        sm.cnt[tid] = 0;
        #pragma unroll
        for (int t = 0; t < MSEL; ++t) sm.best[tid][t] = 0xFFFFFFFFFFFFFFFFull;
    }
    __syncthreads();

    for (int jt = 0; jt < NN / BN; ++jt) {
        const int j0 = jt * BN;
        {
            const float4* src = (const float4*)(feats + (size_t)j0 * DD);
            #pragma unroll
            for (int t = 0; t < 16; ++t) {
                int idx = t * 256 + tid;
                int r = idx >> 6, c4 = idx & 63;
                float4 v = src[idx];
                uint4 u = make_uint4(f2tf(v.x), f2tf(v.y), f2tf(v.z), f2tf(v.w));
                *(uint4*)&sm.Bs[r][c4 * 4] = u;
            }
        }
        if (tid < BN) sm.sqB[tid] = g_sq[j0 + tid];
        __syncthreads();

        float acc[4][4];
        #pragma unroll
        for (int nt = 0; nt < 4; ++nt)
            #pragma unroll
            for (int e = 0; e < 4; ++e) acc[nt][e] = 0.f;

        const int ar = wr * 16 + g;
        #pragma unroll 4
        for (int k = 0; k < DD; k += 8) {
            unsigned int a0 = __float_as_uint(sm.As[ar    ][k + q]);
            unsigned int a1 = __float_as_uint(sm.As[ar + 8][k + q]);
            unsigned int a2 = __float_as_uint(sm.As[ar    ][k + 4 + q]);
            unsigned int a3 = __float_as_uint(sm.As[ar + 8][k + 4 + q]);
            #pragma unroll
            for (int nt = 0; nt < 4; ++nt) {
                const int bn = wc * 32 + nt * 8 + g;
                unsigned int b0 = __float_as_uint(sm.Bs[bn][k + q]);
                unsigned int b1 = __float_as_uint(sm.Bs[bn][k + 4 + q]);
                asm volatile(
                    "mma.sync.aligned.m16n8k8.row.col.f32.tf32.tf32.f32 "
                    "{%0,%1,%2,%3}, {%4,%5,%6,%7}, {%8,%9}, {%0,%1,%2,%3};"
                    : "+f"(acc[nt][0]), "+f"(acc[nt][1]), "+f"(acc[nt][2]), "+f"(acc[nt][3])
                    : "r"(a0), "r"(a1), "r"(a2), "r"(a3), "r"(b0), "r"(b1));
            }
        }

        #pragma unroll
        for (int nt = 0; nt < 4; ++nt) {
            const int cb = wc * 32 + nt * 8 + 2 * q;
            sm.Ss[wr * 16 + g    ][cb    ] = acc[nt][0];
            sm.Ss[wr * 16 + g    ][cb + 1] = acc[nt][1];
            sm.Ss[wr * 16 + g + 8][cb    ] = acc[nt][2];
            sm.Ss[wr * 16 + g + 8][cb + 1] = acc[nt][3];
        }
        __syncthreads();

        #pragma unroll
        for (int a = 0; a < 4; ++a) {
            const int r = ty + 16 * a;
            const float thr = sm.thr[r];
            #pragma unroll
            for (int b = 0; b < 4; ++b) {
                const int c = tx + 16 * b;
                float val = fmaf(-2.f, sm.Ss[r][c], sm.sqB[c]);
                if (val < thr) {
                    int p = atomicAdd(&sm.cnt[r], 1);   // <= BN per row per tile
                    sm.cand[r][p] = ((unsigned long long)mono(val) << 32)
                                  | (unsigned int)(j0 + c);
                }
            }
        }
        __syncthreads();

        if (tid < BM) {
            int n = sm.cnt[tid];
            sm.cnt[tid] = 0;
            for (int qq = 0; qq < n; ++qq) {
                unsigned long long key = sm.cand[tid][qq];
                if (key < sm.best[tid][MSEL - 1]) {
                    int p = MSEL - 1;
                    while (p > 0 && sm.best[tid][p - 1] > key) {
                        sm.best[tid][p] = sm.best[tid][p - 1];
                        --p;
                    }
                    sm.best[tid][p] = key;
                }
            }
            unsigned int mt = (unsigned int)(sm.best[tid][MSEL - 1] >> 32);
            unsigned int u = (mt & 0x80000000u) ? (mt ^ 0x80000000u) : ~mt;
            sm.thr[tid] = __uint_as_float(u);
        }
        __syncthreads();
    }

    for (int idx = tid; idx < BM * MSEL; idx += 256) {
        int r = idx / MSEL, t = idx % MSEL;
        g_cand[(size_t)(i0 + r) * MSEL + t] = sm.best[r][t];
    }
}

// ---------------- Kernel B2: exact fp32 refine of 32 survivors -> exact top-17 ----------------
__global__ void refine_kernel(const float* __restrict__ feats) {
    int row = (blockIdx.x * blockDim.x + threadIdx.x) >> 5;
    int lane = threadIdx.x & 31;
    if (row >= NN) return;

    const float* base = feats + (size_t)row * DD;
    float4 a0 = *(const float4*)(base + lane * 4);
    float4 a1 = *(const float4*)(base + 128 + lane * 4);
    float own[8] = {a0.x, a0.y, a0.z, a0.w, a1.x, a1.y, a1.z, a1.w};

    // exact key for candidate `lane`
    unsigned long long approx = g_cand[(size_t)row * MSEL + lane];
    unsigned long long mykey = 0xFFFFFFFFFFFFFFFFull;

    for (int t = 0; t < MSEL; ++t) {
        unsigned long long ak = __shfl_sync(0xffffffffu, approx, t);
        if (ak == 0xFFFFFFFFFFFFFFFFull) continue;
        int j = (int)(unsigned int)(ak & 0xffffffffull);
        const float* nb = feats + (size_t)j * DD;
        float4 b0 = *(const float4*)(nb + lane * 4);
        float4 b1 = *(const float4*)(nb + 128 + lane * 4);
        float p = own[0]*b0.x + own[1]*b0.y + own[2]*b0.z + own[3]*b0.w
                + own[4]*b1.x + own[5]*b1.y + own[6]*b1.z + own[7]*b1.w;
        #pragma unroll
        for (int o = 16; o; o >>= 1) p += __shfl_xor_sync(0xffffffffu, p, o);
        float val = fmaf(-2.f, p, g_sq[j]);            // sq_j - 2*s (sq_i const per row)
        if (lane == t)
            mykey = ((unsigned long long)mono(val) << 32) | (unsigned int)j;
    }

    // in-warp exact ranking (keys unique via col bits)
    int rank = 0;
    #pragma unroll
    for (int s = 0; s < 32; ++s) {
        unsigned long long ok = __shfl_sync(0xffffffffu, mykey, s);
        if (ok < mykey) ++rank;
    }
    if (rank < KSEL && mykey != 0xFFFFFFFFFFFFFFFFull)
        g_best[(size_t)row * KSEL + rank] = mykey;
}

// ---------------- Kernel C: mutual mask + sparse softmax + AV + residual + normalize ----------------
__global__ void fuse_kernel(const float* __restrict__ feats, float* __restrict__ out) {
    int gw = (blockIdx.x * blockDim.x + threadIdx.x) >> 5;
    int lane = threadIdx.x & 31;
    if (gw >= NN) return;
    const int row = gw;
    const float* base = feats + (size_t)row * DD;
    float4 a0 = *(const float4*)(base + lane * 4);
    float4 a1 = *(const float4*)(base + 128 + lane * 4);
    float own[8] = {a0.x, a0.y, a0.z, a0.w, a1.x, a1.y, a1.z, a1.w};

    int my_nbr = -1;
    int cnt = 0;
    #pragma unroll
    for (int t = 0; t < KSEL; ++t) {
        unsigned long long key = g_best[(size_t)row * KSEL + t];
        int j = (int)(unsigned int)(key & 0xffffffffull);
        if (j != row && cnt < KK) {
            if (cnt == lane) my_nbr = j;
            cnt++;
        }
    }

    bool found = false;
    if (lane < KK && my_nbr >= 0) {
        #pragma unroll
        for (int t = 0; t < KSEL; ++t) {
            unsigned long long key = g_best[(size_t)my_nbr * KSEL + t];
            if ((int)(unsigned int)(key & 0xffffffffull) == row) found = true;
        }
    }
    unsigned int mmask = __ballot_sync(0xffffffffu, found) & 0xffffu;

    float m = 1.0f, Z = 1.0f;
    float acc[8];
    #pragma unroll
    for (int e = 0; e < 8; ++e) acc[e] = own[e];

    for (int l = 0; l < KK; ++l) {
        if (!((mmask >> l) & 1u)) continue;
        int j = __shfl_sync(0xffffffffu, my_nbr, l);
        const float* nb = feats + (size_t)j * DD;
        float4 b0 = *(const float4*)(nb + lane * 4);
        float4 b1 = *(const float4*)(nb + 128 + lane * 4);
        float v[8] = {b0.x, b0.y, b0.z, b0.w, b1.x, b1.y, b1.z, b1.w};
        float p = 0.f;
        #pragma unroll
        for (int e = 0; e < 8; ++e) p = fmaf(own[e], v[e], p);
        #pragma unroll
        for (int o = 16; o; o >>= 1) p += __shfl_xor_sync(0xffffffffu, p, o);
        if (p > m) {
            float f = expf(m - p);
            Z = Z * f + 1.0f;
            #pragma unroll
            for (int e = 0; e < 8; ++e) acc[e] = fmaf(acc[e], f, v[e]);
            m = p;
        } else {
            float wgt = expf(p - m);
            Z += wgt;
            #pragma unroll
            for (int e = 0; e < 8; ++e) acc[e] = fmaf(wgt, v[e], acc[e]);
        }
    }

    float invZ = 1.0f / Z;
    float fcm[8];
    float ss = 0.f;
    #pragma unroll
    for (int e = 0; e < 8; ++e) {
        fcm[e] = fmaf(acc[e], invZ, own[e]);
        ss = fmaf(fcm[e], fcm[e], ss);
    }
    #pragma unroll
    for (int o = 16; o; o >>= 1) ss += __shfl_xor_sync(0xffffffffu, ss, o);
    float inv = 1.0f / fmaxf(sqrtf(ss), 1e-12f);

    float* op = out + (size_t)row * DD;
    *(float4*)(op + lane * 4)       = make_float4(fcm[0]*inv, fcm[1]*inv, fcm[2]*inv, fcm[3]*inv);
    *(float4*)(op + 128 + lane * 4) = make_float4(fcm[4]*inv, fcm[5]*inv, fcm[6]*inv, fcm[7]*inv);
}

// ---------------- launch ----------------
extern "C" void kernel_launch(void* const* d_in, const int* in_sizes, int n_in,
                              void* d_out, int out_size) {
    const float* feats = (const float*)d_in[0];
    float* out = (float*)d_out;
    (void)in_sizes; (void)n_in; (void)out_size;

    cudaFuncSetAttribute(knn_kernel, cudaFuncAttributeMaxDynamicSharedMemorySize,
                         (int)sizeof(SmemB));

    sq_kernel<<<NN / 8, 256>>>(feats);
    knn_kernel<<<NN / BM, 256, sizeof(SmemB)>>>(feats);
    refine_kernel<<<NN / 8, 256>>>(feats);
    fuse_kernel<<<NN / 8, 256>>>(feats, out);
}

// round 5
// speedup vs baseline: 2.2726x; 1.8653x over previous
#include <cuda_runtime.h>
#include <cuda_bf16.h>
#include <math.h>

#define NN 8192
#define DD 256
#define KK 16
#define KSEL 17
#define MS 24            // screened survivors per row (bf16 approx)
#define BM 64
#define BN 64
#define JT (NN / BN)     // 128 j-tiles
#define RSB 264          // smem row stride in bf16 elements (528B)

__device__ float g_sq[NN];
__device__ __nv_bfloat162 g_fb16[NN * DD / 2];
__device__ unsigned long long g_cand[NN * MS];
__device__ unsigned long long g_best[NN * KSEL];

__device__ __forceinline__ unsigned smem_u32(const void* p) {
    unsigned a;
    asm("{ .reg .u64 t; cvta.to.shared.u64 t, %1; cvt.u32.u64 %0, t; }" : "=r"(a) : "l"(p));
    return a;
}
__device__ __forceinline__ unsigned mono(float f) {
    unsigned u = __float_as_uint(f);
    return (u & 0x80000000u) ? ~u : (u | 0x80000000u);
}
__device__ __forceinline__ float unmono(unsigned u) {
    return __uint_as_float((u & 0x80000000u) ? (u ^ 0x80000000u) : ~u);
}

#define CP16(dst, src) asm volatile("cp.async.cg.shared.global [%0], [%1], 16;" :: "r"(dst), "l"(src) : "memory")
#define CP_COMMIT()    asm volatile("cp.async.commit_group;" ::: "memory")
#define CP_WAIT(n)     asm volatile("cp.async.wait_group %0;" :: "n"(n) : "memory")
#define LDSM_X4(r0, r1, r2, r3, a) \
    asm volatile("ldmatrix.sync.aligned.m8n8.x4.shared.b16 {%0,%1,%2,%3}, [%4];" \
        : "=r"(r0), "=r"(r1), "=r"(r2), "=r"(r3) : "r"(a))
#define MMA_BF16(c, a0, a1, a2, a3, b0, b1) \
    asm volatile("mma.sync.aligned.m16n8k16.row.col.f32.bf16.bf16.f32 " \
        "{%0,%1,%2,%3},{%4,%5,%6,%7},{%8,%9},{%0,%1,%2,%3};" \
        : "+f"((c)[0]), "+f"((c)[1]), "+f"((c)[2]), "+f"((c)[3]) \
        : "r"(a0), "r"(a1), "r"(a2), "r"(a3), "r"(b0), "r"(b1))

// ---------------- Kernel A: norms + bf16 convert ----------------
__global__ void sq_kernel(const float* __restrict__ feats) {
    int gw = (blockIdx.x * blockDim.x + threadIdx.x) >> 5;
    int lane = threadIdx.x & 31;
    if (gw >= NN) return;
    const float4* rowp = (const float4*)(feats + (size_t)gw * DD);
    float4 a = rowp[lane];
    float4 b = rowp[lane + 32];
    float s = a.x*a.x + a.y*a.y + a.z*a.z + a.w*a.w
            + b.x*b.x + b.y*b.y + b.z*b.z + b.w*b.w;
    #pragma unroll
    for (int o = 16; o; o >>= 1) s += __shfl_xor_sync(0xffffffffu, s, o);
    if (lane == 0) g_sq[gw] = s;
    __nv_bfloat162* dst = g_fb16 + (size_t)gw * (DD / 2);
    dst[lane * 2]          = __floats2bfloat162_rn(a.x, a.y);
    dst[lane * 2 + 1]      = __floats2bfloat162_rn(a.z, a.w);
    dst[64 + lane * 2]     = __floats2bfloat162_rn(b.x, b.y);
    dst[64 + lane * 2 + 1] = __floats2bfloat162_rn(b.z, b.w);
}

// ---------------- Kernel B: bf16 mma.sync screening -> approx top-24 per row ----------------
struct SmemK {
    __nv_bfloat16 A[BM][RSB];          // 33792 B
    __nv_bfloat16 B[2][BN][RSB];       // 67584 B
    float sqB[2][BN];
    float thr[BM];
    int   cnt[BM];
    unsigned long long best[BM][MS];   // 12288 B
    unsigned long long cand[BM][BN];   // 32768 B
};

__device__ __forceinline__ void prefetch_B(SmemK& sm, int s, int j0, int tid) {
    #pragma unroll
    for (int t = 0; t < 8; ++t) {
        int idx = t * 256 + tid;
        int r = idx >> 5, ch = idx & 31;
        unsigned dst = smem_u32(&sm.B[s][r][ch * 8]);
        const void* src = (const char*)g_fb16 + (((size_t)(j0 + r) * DD) + ch * 8) * 2;
        CP16(dst, src);
    }
    if (tid < 16) {
        unsigned dst = smem_u32(&sm.sqB[s][tid * 4]);
        const void* src = g_sq + j0 + tid * 4;
        CP16(dst, src);
    }
}

__global__ void __launch_bounds__(256, 1) knn_kernel() {
    extern __shared__ char raw[];
    SmemK& sm = *reinterpret_cast<SmemK*>(raw);
    const int tid = threadIdx.x;
    const int lane = tid & 31;
    const int w = tid >> 5;
    const int wr = w >> 1;             // 0..3 -> 16-row strip
    const int wc = w & 1;              // 0..1 -> 32-col half
    const int i0 = blockIdx.x * BM;

    // A tile prefetch (once)
    #pragma unroll
    for (int t = 0; t < 8; ++t) {
        int idx = t * 256 + tid;
        int r = idx >> 5, ch = idx & 31;
        unsigned dst = smem_u32(&sm.A[r][ch * 8]);
        const void* src = (const char*)g_fb16 + (((size_t)(i0 + r) * DD) + ch * 8) * 2;
        CP16(dst, src);
    }
    CP_COMMIT();
    prefetch_B(sm, 0, 0, tid);
    CP_COMMIT();

    if (tid < BM) {
        sm.thr[tid] = __int_as_float(0x7f800000);
        sm.cnt[tid] = 0;
        #pragma unroll
        for (int t = 0; t < MS; ++t) sm.best[tid][t] = 0xFF800000FFFFFFFFull;
    }

    // ldmatrix source addresses
    const unsigned aAddr = smem_u32(&sm.A[wr * 16 + (lane & 15)][0]) + ((lane >> 4) << 4);
    const int rowB = wc * 32 + ((lane >> 4) << 3) + (lane & 7);
    const unsigned bColOff = ((lane >> 3) & 1) << 4;
    unsigned bAddrBase[2];
    bAddrBase[0] = smem_u32(&sm.B[0][rowB][0]) + bColOff;
    bAddrBase[1] = smem_u32(&sm.B[1][rowB][0]) + bColOff;

    const int R0 = wr * 16 + (lane >> 2);
    const int R1 = R0 + 8;
    const int cBase = wc * 32 + 2 * (lane & 3);

    for (int jt = 0; jt < JT; ++jt) {
        const int s = jt & 1;
        const int j0 = jt * BN;

        if (jt + 1 < JT) {
            prefetch_B(sm, s ^ 1, (jt + 1) * BN, tid);
            CP_COMMIT();
            CP_WAIT(1);
        } else {
            CP_WAIT(0);
        }
        __syncthreads();   // B[s]+sqB[s] visible; prev flush (thr/best/cnt) visible

        // MMA: warp tile 16x32, 16 k-steps of k16
        float acc[4][4];
        #pragma unroll
        for (int nt = 0; nt < 4; ++nt)
            #pragma unroll
            for (int e = 0; e < 4; ++e) acc[nt][e] = 0.f;

        const unsigned bA = bAddrBase[s];
        #pragma unroll
        for (int ks = 0; ks < 16; ++ks) {
            unsigned a0, a1, a2, a3;
            LDSM_X4(a0, a1, a2, a3, aAddr + ks * 32);
            unsigned p00, p01, p10, p11, q00, q01, q10, q11;
            LDSM_X4(p00, p01, p10, p11, bA + ks * 32);                 // n-tiles 0,1
            LDSM_X4(q00, q01, q10, q11, bA + 16 * (RSB * 2) + ks * 32); // n-tiles 2,3
            MMA_BF16(acc[0], a0, a1, a2, a3, p00, p01);
            MMA_BF16(acc[1], a0, a1, a2, a3, p10, p11);
            MMA_BF16(acc[2], a0, a1, a2, a3, q00, q01);
            MMA_BF16(acc[3], a0, a1, a2, a3, q10, q11);
        }

        // scan accumulators directly
        const float t0 = sm.thr[R0];
        const float t1 = sm.thr[R1];
        const float* sq = sm.sqB[s];
        #pragma unroll
        for (int nt = 0; nt < 4; ++nt) {
            const int c = cBase + nt * 8;
            float v00 = fmaf(-2.f, acc[nt][0], sq[c]);
            float v01 = fmaf(-2.f, acc[nt][1], sq[c + 1]);
            float v10 = fmaf(-2.f, acc[nt][2], sq[c]);
            float v11 = fmaf(-2.f, acc[nt][3], sq[c + 1]);
            if (v00 < t0) { int p = atomicAdd(&sm.cnt[R0], 1);
                sm.cand[R0][p] = ((unsigned long long)mono(v00) << 32) | (unsigned)(j0 + c); }
            if (v01 < t0) { int p = atomicAdd(&sm.cnt[R0], 1);
                sm.cand[R0][p] = ((unsigned long long)mono(v01) << 32) | (unsigned)(j0 + c + 1); }
            if (v10 < t1) { int p = atomicAdd(&sm.cnt[R1], 1);
                sm.cand[R1][p] = ((unsigned long long)mono(v10) << 32) | (unsigned)(j0 + c); }
            if (v11 < t1) { int p = atomicAdd(&sm.cnt[R1], 1);
                sm.cand[R1][p] = ((unsigned long long)mono(v11) << 32) | (unsigned)(j0 + c + 1); }
        }
        __syncthreads();

        // flush: one thread per row
        if (tid < BM) {
            int n = sm.cnt[tid];
            if (n) {
                sm.cnt[tid] = 0;
                unsigned long long* bl = sm.best[tid];
                for (int q = 0; q < n; ++q) {
                    unsigned long long key = sm.cand[tid][q];
                    if (key < bl[MS - 1]) {
                        int p = MS - 1;
                        while (p > 0 && bl[p - 1] > key) { bl[p] = bl[p - 1]; --p; }
                        bl[p] = key;
                    }
                }
                sm.thr[tid] = unmono((unsigned)(bl[MS - 1] >> 32));
            }
        }
        // next iteration's barrier orders flush before the next scan
    }
    __syncthreads();

    for (int idx = tid; idx < BM * MS; idx += 256) {
        int r = idx / MS, t = idx % MS;
        g_cand[(size_t)(i0 + r) * MS + t] = sm.best[r][t];
    }
}

// ---------------- Kernel B2: exact fp32 refine of 24 survivors -> exact top-17 ----------------
__global__ void refine_kernel(const float* __restrict__ feats) {
    int row = (blockIdx.x * blockDim.x + threadIdx.x) >> 5;
    int lane = threadIdx.x & 31;
    if (row >= NN) return;

    const float* base = feats + (size_t)row * DD;
    float4 a0 = *(const float4*)(base + lane * 4);
    float4 a1 = *(const float4*)(base + 128 + lane * 4);
    float own[8] = {a0.x, a0.y, a0.z, a0.w, a1.x, a1.y, a1.z, a1.w};

    unsigned long long mykey = 0xFFFFFFFFFFFFFFFFull;

    #pragma unroll 4
    for (int t = 0; t < MS; ++t) {
        unsigned long long ak = g_cand[(size_t)row * MS + t];
        int j = (int)(unsigned)(ak & 0xffffffffull);
        const float* nb = feats + (size_t)j * DD;
        float4 b0 = *(const float4*)(nb + lane * 4);
        float4 b1 = *(const float4*)(nb + 128 + lane * 4);
        float p = own[0]*b0.x + own[1]*b0.y + own[2]*b0.z + own[3]*b0.w
                + own[4]*b1.x + own[5]*b1.y + own[6]*b1.z + own[7]*b1.w;
        #pragma unroll
        for (int o = 16; o; o >>= 1) p += __shfl_xor_sync(0xffffffffu, p, o);
        float val = fmaf(-2.f, p, g_sq[j]);
        if (lane == t)
            mykey = ((unsigned long long)mono(val) << 32) | (unsigned)j;
    }

    int rank = 0;
    #pragma unroll
    for (int s = 0; s < MS; ++s) {
        unsigned long long ok = __shfl_sync(0xffffffffu, mykey, s);
        rank += (ok < mykey);
    }
    if (lane < MS && rank < KSEL)
        g_best[(size_t)row * KSEL + rank] = mykey;
}

// ---------------- Kernel C: mutual mask + sparse softmax + AV + residual + normalize ----------------
__global__ void fuse_kernel(const float* __restrict__ feats, float* __restrict__ out) {
    int gw = (blockIdx.x * blockDim.x + threadIdx.x) >> 5;
    int lane = threadIdx.x & 31;
    if (gw >= NN) return;
    const int row = gw;
    const float* base = feats + (size_t)row * DD;
    float4 a0 = *(const float4*)(base + lane * 4);
    float4 a1 = *(const float4*)(base + 128 + lane * 4);
    float own[8] = {a0.x, a0.y, a0.z, a0.w, a1.x, a1.y, a1.z, a1.w};

    int my_nbr = -1;
    int cnt = 0;
    #pragma unroll
    for (int t = 0; t < KSEL; ++t) {
        unsigned long long key = g_best[(size_t)row * KSEL + t];
        int j = (int)(unsigned)(key & 0xffffffffull);
        if (j != row && cnt < KK) {
            if (cnt == lane) my_nbr = j;
            cnt++;
        }
    }

    bool found = false;
    if (lane < KK && my_nbr >= 0) {
        #pragma unroll
        for (int t = 0; t < KSEL; ++t) {
            unsigned long long key = g_best[(size_t)my_nbr * KSEL + t];
            if ((int)(unsigned)(key & 0xffffffffull) == row) found = true;
        }
    }
    unsigned mmask = __ballot_sync(0xffffffffu, found) & 0xffffu;

    float m = 1.0f, Z = 1.0f;
    float acc[8];
    #pragma unroll
    for (int e = 0; e < 8; ++e) acc[e] = own[e];

    for (int l = 0; l < KK; ++l) {
        if (!((mmask >> l) & 1u)) continue;
        int j = __shfl_sync(0xffffffffu, my_nbr, l);
        const float* nb = feats + (size_t)j * DD;
        float4 b0 = *(const float4*)(nb + lane * 4);
        float4 b1 = *(const float4*)(nb + 128 + lane * 4);
        float v[8] = {b0.x, b0.y, b0.z, b0.w, b1.x, b1.y, b1.z, b1.w};
        float p = 0.f;
        #pragma unroll
        for (int e = 0; e < 8; ++e) p = fmaf(own[e], v[e], p);
        #pragma unroll
        for (int o = 16; o; o >>= 1) p += __shfl_xor_sync(0xffffffffu, p, o);
        if (p > m) {
            float f = expf(m - p);
            Z = Z * f + 1.0f;
            #pragma unroll
            for (int e = 0; e < 8; ++e) acc[e] = fmaf(acc[e], f, v[e]);
            m = p;
        } else {
            float wgt = expf(p - m);
            Z += wgt;
            #pragma unroll
            for (int e = 0; e < 8; ++e) acc[e] = fmaf(wgt, v[e], acc[e]);
        }
    }

    float invZ = 1.0f / Z;
    float fcm[8];
    float ss = 0.f;
    #pragma unroll
    for (int e = 0; e < 8; ++e) {
        fcm[e] = fmaf(acc[e], invZ, own[e]);
        ss = fmaf(fcm[e], fcm[e], ss);
    }
    #pragma unroll
    for (int o = 16; o; o >>= 1) ss += __shfl_xor_sync(0xffffffffu, ss, o);
    float inv = 1.0f / fmaxf(sqrtf(ss), 1e-12f);

    float* op = out + (size_t)row * DD;
    *(float4*)(op + lane * 4)       = make_float4(fcm[0]*inv, fcm[1]*inv, fcm[2]*inv, fcm[3]*inv);
    *(float4*)(op + 128 + lane * 4) = make_float4(fcm[4]*inv, fcm[5]*inv, fcm[6]*inv, fcm[7]*inv);
}

// ---------------- launch ----------------
extern "C" void kernel_launch(void* const* d_in, const int* in_sizes, int n_in,
                              void* d_out, int out_size) {
    const float* feats = (const float*)d_in[0];
    float* out = (float*)d_out;
    (void)in_sizes; (void)n_in; (void)out_size;

    cudaFuncSetAttribute(knn_kernel, cudaFuncAttributeMaxDynamicSharedMemorySize,
                         (int)sizeof(SmemK));

    sq_kernel<<<NN / 8, 256>>>(feats);
    knn_kernel<<<NN / BM, 256, sizeof(SmemK)>>>();
    refine_kernel<<<NN / 8, 256>>>(feats);
    fuse_kernel<<<NN / 8, 256>>>(feats, out);
}